// round 12
// baseline (speedup 1.0000x reference)
#include <cuda_runtime.h>
#include <cstdint>

#define B_ 64
#define T_ 96
#define NV 4
#define NF_ 17
#define HW_ 400
#define SIGLEN_ 306
#define KTOT_ 122400        // HW_*SIGLEN_
#define NCHUNK_ 255
#define KC_ 480             // NCHUNK_*KC_ == KTOT_

#define NPX_ 32             // pixels per block
#define THR_ 128            // 4 warps: warp = sig quadrant = conv channel group
#define NBLK_ 13            // ceil(400/32)
#define XSZ_ 440            // halo: 4 vars x 5 rows x 22 cols
#define FP_ 33              // feat tile row pitch
#define AP_ 136             // antisym entries per pixel (17*8)

__device__ float g_sig [(size_t)B_ * HW_ * SIGLEN_];
__device__ float g_part[(size_t)NCHUNK_ * 64 * 32];
__device__ float g_A[(size_t)2 * B_ * AP_ * HW_];   // partial antisym sums
__device__ float g_P[(size_t)2 * B_ * NF_ * HW_];   // [0]=p0 features, [1]=p95

// ---------------------------------------------------------------------------
// Antisymmetric signature step for quadrant Q (offsets 2Q+1, 2Q+2):
// load cur (17 LDS), A[a][e] += prev_a*cur_b - cur_a*prev_b, b=(a+2Q+1+e)%17.
// ---------------------------------------------------------------------------
template<int Q>
__device__ __forceinline__ void sig_step(const float* __restrict__ ft, int pp,
                                         float (&cu)[17], const float (&pv)[17],
                                         float (&acc)[34])
{
#pragma unroll
    for (int f = 0; f < 17; f++) cu[f] = ft[f * FP_ + pp];
#pragma unroll
    for (int a = 0; a < 17; a++) {
        const int b0 = (a + 2 * Q + 1) % 17;
        const int b1 = (a + 2 * Q + 2) % 17;
        float t0 = fmaf(pv[a], cu[b0], acc[2 * a]);
        acc[2 * a]     = fmaf(-cu[a], pv[b0], t0);
        float t1 = fmaf(pv[a], cu[b1], acc[2 * a + 1]);
        acc[2 * a + 1] = fmaf(-cu[a], pv[b1], t1);
    }
}

// ---------------------------------------------------------------------------
// Fused conv3x3(4->12) + feature assembly + antisym partial signature.
// Grid (13, 64, 2): z = T-half. half 0: steps k=1..48 (prev=p_0, writes p0);
// half 1: steps k=49..95 (prev=p_48, writes p95). Partial A -> g_A[half].
// Block = 32 raster pixels, 128 thr; warp = quadrant = conv channel group.
// One __syncthreads per t; xs/feat double-buffered by absolute parity of k.
// ---------------------------------------------------------------------------
__global__ __launch_bounds__(THR_, 4)
void fused_conv_sig_kernel(const float* __restrict__ x,
                           const float* __restrict__ cw,
                           const float* __restrict__ cb)
{
    __shared__ __align__(16) float xs[2][XSZ_];
    __shared__ __align__(16) float ws2[12 * 48];
    __shared__ float wb[12];
    __shared__ __align__(16) float feat[2][17 * FP_];

    const int bxi  = blockIdx.x;
    const int b    = blockIdx.y;
    const int half = blockIdx.z;
    const int tp   = half * 48;           // prologue timestep (prev = p_tp)
    const int kend = half ? 95 : 48;
    const int tid  = threadIdx.x;
    const int lane = tid & 31;
    const int wq   = tid >> 5;
    const int pbase = bxi * NPX_;
    const bool valid = (pbase + lane) < HW_;
    const int pxg = valid ? (pbase + lane) : (HW_ - 1);
    const int r0 = pbase / 20;

    for (int i = tid; i < 2 * XSZ_; i += THR_) (&xs[0][0])[i] = 0.f;
    for (int i = tid; i < 432; i += THR_) {
        const int k = i / 36, r = i % 36, v = r / 9, tap = r % 9;
        ws2[k * 48 + v * 12 + tap] = cw[i];
    }
    if (tid < 12) wb[tid] = cb[tid];

    const float* xg = x + (size_t)b * T_ * NV * HW_;
    int gof[4];
#pragma unroll
    for (int l = 0; l < 4; l++) {
        const int i = tid + l * THR_;
        gof[l] = -1;
        if (i < XSZ_) {
            const int v = i / 110, r = i % 110, rr = r / 22, col = r % 22;
            const int gr = r0 - 1 + rr;
            if (gr >= 0 && gr < 20 && col >= 1 && col <= 20)
                gof[l] = v * HW_ + gr * 20 + (col - 1);
        }
    }

    const int prow = pxg / 20 - r0;
    const int pcol = pxg % 20;
    const int xoff = prow * 22 + pcol;
    const int k0ch = 3 * wq;

    // stage x_tp into xs[0] (tp even), prefetch x_{tp+1}
    float rv[4] = {0.f, 0.f, 0.f, 0.f};
    {
        const float* x0 = xg + (size_t)tp * NV * HW_;
#pragma unroll
        for (int l = 0; l < 4; l++) if (gof[l] >= 0) rv[l] = x0[gof[l]];
#pragma unroll
        for (int l = 0; l < 4; l++) if (gof[l] >= 0) xs[0][tid + l * THR_] = rv[l];
        const float* xn = xg + (size_t)(tp + 1) * NV * HW_;
#pragma unroll
        for (int l = 0; l < 4; l++) if (gof[l] >= 0) rv[l] = xn[gof[l]];
    }
    __syncthreads();

    const float bi0 = wb[k0ch], bi1 = wb[k0ch + 1], bi2 = wb[k0ch + 2];

#define CONV_STEP(XB, FT, TVAL)                                            \
    {                                                                      \
        const float* xrow = (XB) + xoff;                                   \
        float a0 = bi0, a1 = bi1, a2 = bi2;                                \
        _Pragma("unroll")                                                  \
        for (int v = 0; v < 4; v++) {                                      \
            float xv[9];                                                   \
            _Pragma("unroll")                                              \
            for (int dy = 0; dy < 3; dy++)                                 \
                _Pragma("unroll")                                          \
                for (int dx = 0; dx < 3; dx++)                             \
                    xv[dy * 3 + dx] = xrow[v * 110 + dy * 22 + dx];        \
            _Pragma("unroll")                                              \
            for (int c = 0; c < 3; c++) {                                  \
                const float4* wp = (const float4*)(ws2 + (k0ch + c) * 48 + v * 12); \
                const float4 w0 = wp[0];                                   \
                const float4 w1 = wp[1];                                   \
                const float w8 = ws2[(k0ch + c) * 48 + v * 12 + 8];        \
                float s = xv[0] * w0.x;                                    \
                s = fmaf(xv[1], w0.y, s);                                  \
                s = fmaf(xv[2], w0.z, s);                                  \
                s = fmaf(xv[3], w0.w, s);                                  \
                s = fmaf(xv[4], w1.x, s);                                  \
                s = fmaf(xv[5], w1.y, s);                                  \
                s = fmaf(xv[6], w1.z, s);                                  \
                s = fmaf(xv[7], w1.w, s);                                  \
                s = fmaf(xv[8], w8, s);                                    \
                if (c == 0) a0 += s; else if (c == 1) a1 += s; else a2 += s; \
            }                                                              \
        }                                                                  \
        (FT)[(k0ch + 0) * FP_ + lane] = a0;                                \
        (FT)[(k0ch + 1) * FP_ + lane] = a1;                                \
        (FT)[(k0ch + 2) * FP_ + lane] = a2;                                \
        (FT)[(12 + wq) * FP_ + lane] = xrow[wq * 110 + 23];                \
        if (wq == 0) (FT)[16 * FP_ + lane] = (TVAL);                       \
    }

#define SIG_SWITCH(FT, CUR, PRV)                                           \
    switch (wq) {                                                          \
        case 0:  sig_step<0>((FT), lane, (CUR), (PRV), acc); break;        \
        case 1:  sig_step<1>((FT), lane, (CUR), (PRV), acc); break;        \
        case 2:  sig_step<2>((FT), lane, (CUR), (PRV), acc); break;        \
        default: sig_step<3>((FT), lane, (CUR), (PRV), acc); break;        \
    }

    // prologue: conv(tp) -> feat[0]; stage xs[1]=x_{tp+1}; prefetch x_{tp+2}
    CONV_STEP(xs[0], feat[0], (float)tp * (1.0f / 95.0f))
#pragma unroll
    for (int l = 0; l < 4; l++) if (gof[l] >= 0) xs[1][tid + l * THR_] = rv[l];
    {
        const float* xn = xg + (size_t)(tp + 2) * NV * HW_;
#pragma unroll
        for (int l = 0; l < 4; l++) if (gof[l] >= 0) rv[l] = xn[gof[l]];
    }
    __syncthreads();

    float cuA[17], cuB[17], acc[34];
#pragma unroll
    for (int i = 0; i < 34; i++) acc[i] = 0.f;
#pragma unroll
    for (int f = 0; f < 17; f++) cuA[f] = feat[0][f * FP_ + lane];   // p_tp

    // half 0: emit p0 features now (cuA will be overwritten)
    if (half == 0 && wq == 0 && valid) {
        float* gp = g_P + (size_t)b * NF_ * HW_ + pxg;   // g_P[0][b][f][px]
#pragma unroll
        for (int f = 0; f < 17; f++) gp[f * HW_] = cuA[f];
    }

    // main loop: 24 pairs, odd step k then even step k+1 (guarded)
    for (int kk = 0; kk < 24; kk++) {
        const int k = tp + 2 * kk + 1;          // odd -> cuB
        {
#pragma unroll
            for (int l = 0; l < 4; l++) if (gof[l] >= 0) xs[0][tid + l * THR_] = rv[l];
            const int tn = (k + 2 < T_) ? k + 2 : T_ - 1;
            const float* xn = xg + (size_t)tn * NV * HW_;
#pragma unroll
            for (int l = 0; l < 4; l++) if (gof[l] >= 0) rv[l] = xn[gof[l]];
            CONV_STEP(xs[1], feat[1], (float)k * (1.0f / 95.0f))
            __syncthreads();
            SIG_SWITCH(feat[1], cuB, cuA)
        }
        const int k2 = k + 1;                   // even -> cuA
        if (k2 <= kend) {
#pragma unroll
            for (int l = 0; l < 4; l++) if (gof[l] >= 0) xs[1][tid + l * THR_] = rv[l];
            const int tn = (k2 + 2 < T_) ? k2 + 2 : T_ - 1;
            const float* xn = xg + (size_t)tn * NV * HW_;
#pragma unroll
            for (int l = 0; l < 4; l++) if (gof[l] >= 0) rv[l] = xn[gof[l]];
            CONV_STEP(xs[0], feat[0], (float)k2 * (1.0f / 95.0f))
            __syncthreads();
            SIG_SWITCH(feat[0], cuA, cuB)
        }
    }
#undef CONV_STEP
#undef SIG_SWITCH

    // epilogue: partial A -> g_A[half]; half 1 ends at k=95 (odd) -> p95=cuB
    if (valid) {
        float* ga = g_A + (((size_t)half * B_ + b) * AP_) * HW_ + pxg;
#pragma unroll
        for (int a = 0; a < 17; a++) {
#pragma unroll
            for (int e = 0; e < 2; e++)
                ga[(size_t)(a * 8 + 2 * wq + e) * HW_] = acc[2 * a + e];
        }
        if (half == 1 && wq == 0) {
            float* gp = g_P + ((size_t)B_ + b) * NF_ * HW_ + pxg;  // g_P[1][b][f][px]
#pragma unroll
            for (int f = 0; f < 17; f++) gp[f * HW_] = cuB[f];
        }
    }
}

// ---------------------------------------------------------------------------
// Combine: A = A0+A1; W = A + p95_a*p0_b - p0_a*p95_b;
// lvl2_ab = 0.5*l1_a*l1_b + 0.5*W, lvl2_ba = 0.5*l1_a*l1_b - 0.5*W.
// Q==0 also writes lvl1 and the diagonal.
// ---------------------------------------------------------------------------
template<int Q>
__device__ __forceinline__ void combine_body(float* __restrict__ sg,
                                             const float* __restrict__ ga0,
                                             const float* __restrict__ ga1,
                                             const float (&p0v)[17],
                                             const float (&p95)[17],
                                             const float (&l1)[17])
{
    if (Q == 0) {
#pragma unroll
        for (int f = 0; f < 17; f++) {
            sg[f] = l1[f];
            sg[17 + f * 17 + f] = 0.5f * l1[f] * l1[f];
        }
    }
#pragma unroll
    for (int a = 0; a < 17; a++) {
#pragma unroll
        for (int e = 0; e < 2; e++) {
            const int bb = (a + 2 * Q + 1 + e) % 17;
            const size_t ai = (size_t)(a * 8 + 2 * Q + e) * HW_;
            const float A = ga0[ai] + ga1[ai];
            const float W = A + p95[a] * p0v[bb] - p0v[a] * p95[bb];
            const float S = 0.5f * l1[a] * l1[bb];
            const float D = 0.5f * W;
            sg[17 + a * 17 + bb] = S + D;
            sg[17 + bb * 17 + a] = S - D;
        }
    }
}

__global__ __launch_bounds__(THR_)
void combine_kernel()
{
    const int bxi = blockIdx.x, b = blockIdx.y;
    const int tid = threadIdx.x;
    const int lane = tid & 31, wq = tid >> 5;
    const int px = bxi * NPX_ + lane;
    if (px >= HW_) return;

    float p0v[17], p95[17], l1[17];
    const float* gp0 = g_P + (size_t)b * NF_ * HW_ + px;
    const float* gp1 = g_P + ((size_t)B_ + b) * NF_ * HW_ + px;
#pragma unroll
    for (int f = 0; f < 17; f++) {
        p0v[f] = gp0[f * HW_];
        p95[f] = gp1[f * HW_];
        l1[f] = p95[f] - p0v[f];
    }
    const float* ga0 = g_A + ((size_t)b * AP_) * HW_ + px;
    const float* ga1 = g_A + (((size_t)B_ + b) * AP_) * HW_ + px;
    float* sg = g_sig + ((size_t)b * HW_ + px) * SIGLEN_;

    switch (wq) {
        case 0:  combine_body<0>(sg, ga0, ga1, p0v, p95, l1); break;
        case 1:  combine_body<1>(sg, ga0, ga1, p0v, p95, l1); break;
        case 2:  combine_body<2>(sg, ga0, ga1, p0v, p95, l1); break;
        default: combine_body<3>(sg, ga0, ga1, p0v, p95, l1); break;
    }
}

// ---------------------------------------------------------------------------
// Layer-1 GEMM partials over K=122400, 255 chunks of 480. Reg prefetch.
// ---------------------------------------------------------------------------
__global__ __launch_bounds__(256)
void mlp1_kernel(const float* __restrict__ w1)
{
    __shared__ __align__(16) float ss[32 * 66];
    __shared__ __align__(16) float wsm[32 * 32];

    const int cx = blockIdx.x, tid = threadIdx.x;
    const int oq = tid & 7, bq = tid >> 3;
    const int b0 = bq * 2, o0 = oq * 4;
    const int kb = cx * KC_;

    float ps[8], pw[4];
    {
        const int k0 = kb;
#pragma unroll
        for (int r = 0; r < 8; r++) {
            const int idx = tid + r * 256;
            ps[r] = g_sig[(size_t)(idx >> 5) * KTOT_ + k0 + (idx & 31)];
        }
#pragma unroll
        for (int r = 0; r < 4; r++) {
            const int idx = tid + r * 256;
            pw[r] = w1[(size_t)(k0 + (idx >> 5)) * 32 + (idx & 31)];
        }
    }

    float acc[2][4] = {};

    for (int tile = 0; tile < KC_ / 32; tile++) {
#pragma unroll
        for (int r = 0; r < 8; r++) {
            const int idx = tid + r * 256;
            ss[(idx & 31) * 66 + (idx >> 5)] = ps[r];
        }
#pragma unroll
        for (int r = 0; r < 4; r++) {
            const int idx = tid + r * 256;
            wsm[(idx >> 5) * 32 + (idx & 31)] = pw[r];
        }
        if (tile < KC_ / 32 - 1) {
            const int k0 = kb + (tile + 1) * 32;
#pragma unroll
            for (int r = 0; r < 8; r++) {
                const int idx = tid + r * 256;
                ps[r] = g_sig[(size_t)(idx >> 5) * KTOT_ + k0 + (idx & 31)];
            }
#pragma unroll
            for (int r = 0; r < 4; r++) {
                const int idx = tid + r * 256;
                pw[r] = w1[(size_t)(k0 + (idx >> 5)) * 32 + (idx & 31)];
            }
        }
        __syncthreads();
#pragma unroll
        for (int kk = 0; kk < 32; kk++) {
            const float2 sv = *(const float2*)&ss[kk * 66 + b0];
            const float4 wv = *(const float4*)&wsm[kk * 32 + o0];
            acc[0][0] = fmaf(sv.x, wv.x, acc[0][0]);
            acc[0][1] = fmaf(sv.x, wv.y, acc[0][1]);
            acc[0][2] = fmaf(sv.x, wv.z, acc[0][2]);
            acc[0][3] = fmaf(sv.x, wv.w, acc[0][3]);
            acc[1][0] = fmaf(sv.y, wv.x, acc[1][0]);
            acc[1][1] = fmaf(sv.y, wv.y, acc[1][1]);
            acc[1][2] = fmaf(sv.y, wv.z, acc[1][2]);
            acc[1][3] = fmaf(sv.y, wv.w, acc[1][3]);
        }
        __syncthreads();
    }
#pragma unroll
    for (int i = 0; i < 2; i++)
#pragma unroll
        for (int j = 0; j < 4; j++)
            g_part[((size_t)cx * 64 + b0 + i) * 32 + o0 + j] = acc[i][j];
}

// ---------------------------------------------------------------------------
// Reduce partials + bias/relu + layers 2..4.
// ---------------------------------------------------------------------------
__global__ __launch_bounds__(256)
void mlp_tail_kernel(const float* __restrict__ b1,
                     const float* __restrict__ w2, const float* __restrict__ b2,
                     const float* __restrict__ w3, const float* __restrict__ b3,
                     const float* __restrict__ w4, const float* __restrict__ b4,
                     float* __restrict__ out)
{
    __shared__ float red[8][33];
    const int b = blockIdx.x, tid = threadIdx.x;
    const int o = tid & 31, g = tid >> 5;

    float s = 0.f;
    for (int c = g; c < NCHUNK_; c += 8)
        s += g_part[((size_t)c * 64 + b) * 32 + o];
    red[g][o] = s;
    __syncthreads();

    if (tid < 32) {
        float s1 = b1[o];
#pragma unroll
        for (int gg = 0; gg < 8; gg++) s1 += red[gg][o];
        float h = fmaxf(s1, 0.f);

        float s2 = b2[o];
#pragma unroll
        for (int k = 0; k < 32; k++)
            s2 = fmaf(__shfl_sync(0xffffffffu, h, k), w2[k * 32 + o], s2);
        h = fmaxf(s2, 0.f);

        float s3 = b3[o];
#pragma unroll
        for (int k = 0; k < 32; k++)
            s3 = fmaf(__shfl_sync(0xffffffffu, h, k), w3[k * 32 + o], s3);
        h = fmaxf(s3, 0.f);

        float v = h * w4[o];
#pragma unroll
        for (int off = 16; off; off >>= 1) v += __shfl_xor_sync(0xffffffffu, v, off);
        if (o == 0) out[b] = v + b4[0];
    }
}

// ---------------------------------------------------------------------------
extern "C" void kernel_launch(void* const* d_in, const int* in_sizes, int n_in,
                              void* d_out, int out_size)
{
    const float* x  = (const float*)d_in[0];
    const float* cw = (const float*)d_in[1];
    const float* cb = (const float*)d_in[2];
    const float* w1 = (const float*)d_in[3];
    const float* b1 = (const float*)d_in[4];
    const float* w2 = (const float*)d_in[5];
    const float* b2 = (const float*)d_in[6];
    const float* w3 = (const float*)d_in[7];
    const float* b3 = (const float*)d_in[8];
    const float* w4 = (const float*)d_in[9];
    const float* b4 = (const float*)d_in[10];
    float* out = (float*)d_out;

    fused_conv_sig_kernel<<<dim3(NBLK_, B_, 2), THR_>>>(x, cw, cb);
    combine_kernel<<<dim3(NBLK_, B_), THR_>>>();
    mlp1_kernel<<<NCHUNK_, 256>>>(w1);
    mlp_tail_kernel<<<B_, 256>>>(b1, w2, b2, w3, b3, w4, b4, out);
}